// round 15
// baseline (speedup 1.0000x reference)
#include <cuda_runtime.h>
#include <cuda_fp16.h>
#include <cstdint>

// VQActivation depth-4 residual VQ.
// fp16 mma.sync ranking with PER-WARP cp.async B rings (barrier-free
// mainloop) + serial-fp32 rescoring bitwise-matching the reference.
#define CDIM  256
#define HW    3136
#define NROWS 100352
#define DEPTH 4
#define TM    64
#define NTH   256
#define TAU   0.008f

#define A2_STRIDE  576                    // bytes per row (512 data + 64 pad)
#define OFF_CODE 0                        // 64 ints
#define OFF_SU   256                      // 64 floats
#define OFF_A2   1024
#define A2_BYTES (64*A2_STRIDE)           // 36864
#define OFF_B    (OFF_A2 + A2_BYTES)      // 37888
#define WBUF     2048                     // per-warp per-buffer (32 codes x 64B)
#define NBUF     4
#define OFF_RED  OFF_A2                   // merge scratch / cbS reuse A2
#define SMEM_BYTES (OFF_B + 8*NBUF*WBUF)  // 103424 -> 2 CTAs/SM

__device__ float    g_resid[(size_t)NROWS * CDIM];
__device__ uint16_t g_cbh[1024 * 256];     // fp16 codebook, fragment-permuted

__device__ __forceinline__ void mma16(float* d, uint32_t a0, uint32_t a1,
                                      uint32_t a2, uint32_t a3,
                                      uint32_t b0, uint32_t b1) {
    asm volatile("mma.sync.aligned.m16n8k16.row.col.f32.f16.f16.f32 "
                 "{%0,%1,%2,%3}, {%4,%5,%6,%7}, {%8,%9}, {%0,%1,%2,%3};"
                 : "+f"(d[0]), "+f"(d[1]), "+f"(d[2]), "+f"(d[3])
                 : "r"(a0), "r"(a1), "r"(a2), "r"(a3), "r"(b0), "r"(b1));
}
#define CP16(sm, gp) asm volatile("cp.async.cg.shared.global [%0], [%1], 16;" :: "r"(sm), "l"(gp))
#define CP_COMMIT()  asm volatile("cp.async.commit_group;")
#define CP_WAIT2()   asm volatile("cp.async.wait_group 2;")
#define CP_WAIT1()   asm volatile("cp.async.wait_group 1;")
#define CP_WAIT0()   asm volatile("cp.async.wait_group 0;")
#define LDS128(r0,r1,r2,r3,addr) \
    asm volatile("ld.shared.v4.u32 {%0,%1,%2,%3}, [%4];" \
                 : "=r"(r0), "=r"(r1), "=r"(r2), "=r"(r3) : "r"(addr))

__device__ __forceinline__ uint32_t smem_u32(const void* p) {
    uint32_t a;
    asm("{ .reg .u64 t; cvta.to.shared.u64 t, %1; cvt.u32.u64 %0, t; }" : "=r"(a) : "l"(p));
    return a;
}

// packed half index p (0..255) -> original k:
//   qt=(p>>3)&3, j=p&7:  k = (p>>5)*32 + (j>>2)*16 + ((j>>1)&1)*8 + qt*2 + (j&1)
// note p>>5 = k-chunk, so one (code, k-chunk) fragment = contiguous 64B.
__global__ void prep_cbh(const float* __restrict__ cb) {
    int i = blockIdx.x * 256 + threadIdx.x;
    int p = i & 255, j = p & 7;
    int k = (p >> 5) * 32 + (j >> 2) * 16 + ((j >> 1) & 1) * 8
            + ((p >> 3) & 3) * 2 + (j & 1);
    g_cbh[i] = __half_as_ushort(__float2half_rn(cb[(i & ~255) + k]));
}

__global__ void __launch_bounds__(NTH, 2)
vq_step(const float* __restrict__ x, const float* __restrict__ cb,
        float* __restrict__ out, int iter)
{
    extern __shared__ char smem[];
    const uint32_t sb = smem_u32(smem);
    int*   scode = (int*)(smem + OFF_CODE);
    float* su    = (float*)(smem + OFF_SU);

    const int tid  = threadIdx.x;
    const int lane = tid & 31, w = tid >> 5;
    const int quad = lane >> 2, qt = lane & 3;
    const int wr   = w >> 2;            // rows wr*32..+31
    const int wc   = w & 3;             // codes wc*32..+31 within tile
    const int wrow = wr * 32;
    const int n0   = blockIdx.x * TM;
    const float* src = (iter == 0) ? x : g_resid;
    const bool last = (iter == DEPTH - 1);

    // per-warp B ring: this warp's slice only (32 codes x 32 halves = 2KB)
    const uint32_t wb = sb + OFF_B + (uint32_t)w * (NBUF * WBUF);
    const uint16_t* gsrc0 = g_cbh + ((size_t)(wc * 32 + lane) << 8);
    auto prefetch = [&](int g, int buf) {   // chunk g: code tile g>>3, k g&7
        const uint16_t* gp = gsrc0 + ((g >> 3) << 15) + (g & 7) * 32;
        uint32_t dst = wb + (uint32_t)buf * WBUF + lane * 64;
        CP16(dst,      gp);
        CP16(dst + 16, gp + 8);
        CP16(dst + 32, gp + 16);
        CP16(dst + 48, gp + 24);
        CP_COMMIT();
    };
    prefetch(0, 0);
    prefetch(1, 1);
    prefetch(2, 2);

    // ---- stage: gmem fp32 -> fragment-packed fp16 A2 (cooperative) ----
    {
        int r = tid >> 2, q = tid & 3;      // row 0..63, frag quad-thread
        int n = n0 + r;
        int b = n / HW;
        int hw = n - b * HW;
        const float* sp = src + (size_t)b * (CDIM * HW) + hw;
        uint32_t wbase = sb + OFF_A2 + r * A2_STRIDE + q * 16;
#pragma unroll
        for (int kc = 0; kc < 8; kc++)
#pragma unroll
            for (int jh = 0; jh < 4; jh++) {
                int k0 = kc * 32 + (jh >> 1) * 16 + (jh & 1) * 8 + q * 2;
                __half h0 = __float2half_rn(sp[(size_t)k0 * HW]);
                __half h1 = __float2half_rn(sp[(size_t)(k0 + 1) * HW]);
                uint32_t v = (uint32_t)__half_as_ushort(h0)
                           | ((uint32_t)__half_as_ushort(h1) << 16);
                asm volatile("st.shared.u32 [%0], %1;"
                             :: "r"(wbase + kc * 64 + jh * 4), "r"(v));
            }
    }
    __syncthreads();                       // A2 ready; ONLY mainloop barrier

    float mv[4][2]; int mi[4][2];
#pragma unroll
    for (int i = 0; i < 4; i++)
#pragma unroll
        for (int j = 0; j < 2; j++) { mv[i][j] = -3.0e38f; mi[i][j] = 0; }

    const uint32_t abase = sb + OFF_A2 + (wrow + quad) * A2_STRIDE + qt * 16;
    const uint32_t bbase = wb + quad * 64 + qt * 16;
    for (int ct = 0; ct < 8; ct++) {
        float acc[8][4];
#pragma unroll
        for (int i = 0; i < 8; i++)
#pragma unroll
            for (int j = 0; j < 4; j++) acc[i][j] = 0.0f;

#pragma unroll
        for (int kc = 0; kc < 8; kc++) {
            int g = ct * 8 + kc;
            if (g < 62) CP_WAIT2(); else if (g == 62) CP_WAIT1(); else CP_WAIT0();
            if (g + 3 < 64) prefetch(g + 3, (g + 3) & 3);
            uint32_t Af[4][4], Bf[4][4];
            uint32_t ab = abase + kc * 64;
            LDS128(Af[0][0], Af[0][1], Af[0][2], Af[0][3], ab);
            LDS128(Af[1][0], Af[1][1], Af[1][2], Af[1][3], ab + 8  * A2_STRIDE);
            LDS128(Af[2][0], Af[2][1], Af[2][2], Af[2][3], ab + 16 * A2_STRIDE);
            LDS128(Af[3][0], Af[3][1], Af[3][2], Af[3][3], ab + 24 * A2_STRIDE);
            uint32_t bb = bbase + (uint32_t)(g & 3) * WBUF;
            LDS128(Bf[0][0], Bf[0][1], Bf[0][2], Bf[0][3], bb);
            LDS128(Bf[1][0], Bf[1][1], Bf[1][2], Bf[1][3], bb + 512);
            LDS128(Bf[2][0], Bf[2][1], Bf[2][2], Bf[2][3], bb + 1024);
            LDS128(Bf[3][0], Bf[3][1], Bf[3][2], Bf[3][3], bb + 1536);
#pragma unroll
            for (int s = 0; s < 2; s++)            // two k16 steps
#pragma unroll
                for (int half = 0; half < 2; half++)
#pragma unroll
                    for (int cf = 0; cf < 4; cf++)
                        mma16(acc[half * 4 + cf],
                              Af[half * 2][2 * s],     Af[half * 2 + 1][2 * s],
                              Af[half * 2][2 * s + 1], Af[half * 2 + 1][2 * s + 1],
                              Bf[cf][2 * s], Bf[cf][2 * s + 1]);
        }

        // fold tile into per-thread top-2 (4 owned rows)
#pragma unroll
        for (int cf = 0; cf < 4; cf++)
#pragma unroll
            for (int half = 0; half < 2; half++)
#pragma unroll
                for (int j = 0; j < 4; j++) {
                    float v = acc[half * 4 + cf][j];
                    int lr = half * 2 + (j >> 1);
                    int code = ct * 128 + wc * 32 + cf * 8 + qt * 2 + (j & 1);
                    if (v > mv[lr][0]) {
                        mv[lr][1] = mv[lr][0]; mi[lr][1] = mi[lr][0];
                        mv[lr][0] = v;         mi[lr][0] = code;
                    } else if (v > mv[lr][1]) {
                        mv[lr][1] = v;         mi[lr][1] = code;
                    }
                }
    }

    // ---- merge: 16 partial top-2 sets per row (stride 33); reuses A2 ----
    float* redV = (float*)(smem + OFF_RED);
    int*   redI = (int*)(smem + OFF_RED + 8448);
    __syncthreads();                       // A2 dead from here on
    {
        int slot = wc * 4 + qt;
#pragma unroll
        for (int lr = 0; lr < 4; lr++) {
            int row = wrow + lr * 8 + quad;
            redV[row * 33 + slot * 2 + 0] = mv[lr][0];
            redV[row * 33 + slot * 2 + 1] = mv[lr][1];
            redI[row * 33 + slot * 2 + 0] = mi[lr][0];
            redI[row * 33 + slot * 2 + 1] = mi[lr][1];
        }
    }
    __syncthreads();

    if (tid < TM) {
        float m0 = -3.0e38f, m1 = -3.0e38f, m2 = -3.0e38f, m3 = -3.0e38f;
        int j0 = 0, j1 = 0, j2 = 0, j3 = 0;
#pragma unroll 2
        for (int s = 0; s < 32; s++) {
            float v = redV[tid * 33 + s];
            int   c = redI[tid * 33 + s];
            if (v > m0 || (v == m0 && c < j0)) {
                m3 = m2; j3 = j2; m2 = m1; j2 = j1; m1 = m0; j1 = j0; m0 = v; j0 = c;
            } else if (v > m1 || (v == m1 && c < j1)) {
                m3 = m2; j3 = j2; m2 = m1; j2 = j1; m1 = v; j1 = c;
            } else if (v > m2 || (v == m2 && c < j2)) {
                m3 = m2; j3 = j2; m2 = v; j2 = c;
            } else if (v > m3 || (v == m3 && c < j3)) {
                m3 = v; j3 = c;
            }
        }
        int c0i = j0;
        int c1i = (m0 - m1 <= TAU) ? j1 : j0;
        int c2i = (m0 - m2 <= TAU) ? j2 : j0;
        int c3i = (m0 - m3 <= TAU) ? j3 : j0;

        // serial ascending-k fp32 chains on EXACT residual (gmem re-read):
        // bitwise-replicates the reference accumulation; u = winner's value.
        const int n = n0 + tid;
        const int b = n / HW;
        const int hw = n - b * HW;
        const float* sp = src + (size_t)b * (CDIM * HW) + hw;
        const float4* p0 = (const float4*)(cb + (size_t)c0i * CDIM);
        const float4* p1 = (const float4*)(cb + (size_t)c1i * CDIM);
        const float4* p2 = (const float4*)(cb + (size_t)c2i * CDIM);
        const float4* p3 = (const float4*)(cb + (size_t)c3i * CDIM);
        float s0 = 0.0f, s1 = 0.0f, s2 = 0.0f, s3 = 0.0f;
#pragma unroll 4
        for (int q = 0; q < 64; q++) {
            float a0 = sp[(size_t)(q * 4 + 0) * HW];
            float a1 = sp[(size_t)(q * 4 + 1) * HW];
            float a2 = sp[(size_t)(q * 4 + 2) * HW];
            float a3 = sp[(size_t)(q * 4 + 3) * HW];
            float4 b0 = __ldg(p0 + q), b1 = __ldg(p1 + q);
            float4 b2 = __ldg(p2 + q), b3 = __ldg(p3 + q);
            s0 = fmaf(a0, b0.x, s0); s0 = fmaf(a1, b0.y, s0);
            s0 = fmaf(a2, b0.z, s0); s0 = fmaf(a3, b0.w, s0);
            s1 = fmaf(a0, b1.x, s1); s1 = fmaf(a1, b1.y, s1);
            s1 = fmaf(a2, b1.z, s1); s1 = fmaf(a3, b1.w, s1);
            s2 = fmaf(a0, b2.x, s2); s2 = fmaf(a1, b2.y, s2);
            s2 = fmaf(a2, b2.z, s2); s2 = fmaf(a3, b2.w, s2);
            s3 = fmaf(a0, b3.x, s3); s3 = fmaf(a1, b3.y, s3);
            s3 = fmaf(a2, b3.z, s3); s3 = fmaf(a3, b3.w, s3);
        }
        float bp = s0; int bi = c0i;
        if (s1 > bp || (s1 == bp && c1i < bi)) { bp = s1; bi = c1i; }
        if (s2 > bp || (s2 == bp && c2i < bi)) { bp = s2; bi = c2i; }
        if (s3 > bp || (s3 == bp && c3i < bi)) { bp = s3; bi = c3i; }
        scode[tid] = bi;
        su[tid]    = bp;
    }

    // ---- epilogue: resid = src - cb[code]*u  (mul then sub, exact) ----
    float* cbS = (float*)(smem + OFF_RED);     // 32 x 257 floats, reuses A2
    for (int h = 0; h < 2; h++) {              // rows [32h, 32h+32)
        __syncthreads();
        for (int idx = tid; idx < 32 * 256; idx += NTH) {
            int rl = idx >> 8, c = idx & 255;
            cbS[rl * 257 + c] = cb[(size_t)scode[h * 32 + rl] * CDIM + c];
        }
        __syncthreads();
#pragma unroll 4
        for (int it = 0; it < 32; it++) {
            int idx = tid + it * NTH;
            int rl = idx & 31, c = idx >> 5;
            int r = h * 32 + rl;
            int n = n0 + r;
            int b = n / HW;
            int hw = n - b * HW;
            size_t gidx = (size_t)b * (CDIM * HW) + (size_t)c * HW + hw;
            float val = __fsub_rn(src[gidx],
                                  __fmul_rn(su[r], cbS[rl * 257 + c]));
            if (last) out[gidx] = __fsub_rn(x[gidx], val);
            else      g_resid[gidx] = val;
        }
    }
}

extern "C" void kernel_launch(void* const* d_in, const int* in_sizes, int n_in,
                              void* d_out, int out_size)
{
    const float* x  = (const float*)d_in[0];
    const float* cb = (const float*)d_in[1];
    float* out = (float*)d_out;

    cudaFuncSetAttribute(vq_step, cudaFuncAttributeMaxDynamicSharedMemorySize,
                         SMEM_BYTES);
    prep_cbh<<<1024, 256>>>(cb);
    dim3 grid(NROWS / TM), block(NTH);
    for (int it = 0; it < DEPTH; it++)
        vq_step<<<grid, block, SMEM_BYTES>>>(x, cb, out, it);
}

// round 17
// speedup vs baseline: 1.4997x; 1.4997x over previous
#include <cuda_runtime.h>
#include <cuda_fp16.h>
#include <cstdint>

// VQActivation depth-4 residual VQ — single fused kernel.
// fp16 mma.sync ranking (cooperative coalesced B prefetch, 16KB chunks,
// 2 CTAs/SM) + serial-fp32 rescoring bitwise-matching the reference.
#define CDIM  256
#define HW    3136
#define NROWS 100352
#define DEPTH 4
#define TM    64
#define NTH   256
#define TAU   0.008f

#define A2_STRIDE  576                    // bytes per row (512 data + 64 pad)
#define OFF_CODE 0                        // 64 ints
#define OFF_SU   256                      // 64 floats
#define OFF_A2   1024
#define A2_BYTES (64*A2_STRIDE)           // 36864
#define OFF_B    (OFF_A2 + A2_BYTES)      // 37888
#define CHUNK    16384                    // 128 codes x 64 halves (2 k-chunks)
#define OFF_RED  OFF_A2                   // merge scratch / cbS reuse A2
#define SMEM_BYTES (OFF_B + 3*CHUNK)      // 87040 -> 2 CTAs/SM

__device__ float    g_resid[(size_t)NROWS * CDIM];
__device__ uint16_t g_cbh[1024 * 256];     // fp16 codebook, fragment-permuted

__device__ __forceinline__ void mma16(float* d, uint32_t a0, uint32_t a1,
                                      uint32_t a2, uint32_t a3,
                                      uint32_t b0, uint32_t b1) {
    asm volatile("mma.sync.aligned.m16n8k16.row.col.f32.f16.f16.f32 "
                 "{%0,%1,%2,%3}, {%4,%5,%6,%7}, {%8,%9}, {%0,%1,%2,%3};"
                 : "+f"(d[0]), "+f"(d[1]), "+f"(d[2]), "+f"(d[3])
                 : "r"(a0), "r"(a1), "r"(a2), "r"(a3), "r"(b0), "r"(b1));
}
#define CP16(sm, gp) asm volatile("cp.async.cg.shared.global [%0], [%1], 16;" :: "r"(sm), "l"(gp))
#define CP_COMMIT()  asm volatile("cp.async.commit_group;")
#define CP_WAIT1()   asm volatile("cp.async.wait_group 1;")
#define CP_WAIT0()   asm volatile("cp.async.wait_group 0;")
#define LDS128(r0,r1,r2,r3,addr) \
    asm volatile("ld.shared.v4.u32 {%0,%1,%2,%3}, [%4];" \
                 : "=r"(r0), "=r"(r1), "=r"(r2), "=r"(r3) : "r"(addr))

__device__ __forceinline__ uint32_t smem_u32(const void* p) {
    uint32_t a;
    asm("{ .reg .u64 t; cvta.to.shared.u64 t, %1; cvt.u32.u64 %0, t; }" : "=r"(a) : "l"(p));
    return a;
}

// packed half index p (0..255) -> original k:
//   qt=(p>>3)&3, j=p&7:  k = (p>>5)*32 + (j>>2)*16 + ((j>>1)&1)*8 + qt*2 + (j&1)
// note p>>5 = k-chunk, so one (code, k-chunk) fragment = 64B contiguous.
__global__ void prep_cbh(const float* __restrict__ cb) {
    int i = blockIdx.x * 256 + threadIdx.x;
    int p = i & 255, j = p & 7;
    int k = (p >> 5) * 32 + (j >> 2) * 16 + ((j >> 1) & 1) * 8
            + ((p >> 3) & 3) * 2 + (j & 1);
    g_cbh[i] = __half_as_ushort(__float2half_rn(cb[(i & ~255) + k]));
}

__global__ void __launch_bounds__(NTH, 2)
vq_fused(const float* __restrict__ x, const float* __restrict__ cb,
         float* __restrict__ out)
{
    extern __shared__ char smem[];
    const uint32_t sb = smem_u32(smem);
    int*   scode = (int*)(smem + OFF_CODE);
    float* su    = (float*)(smem + OFF_SU);

    const int tid  = threadIdx.x;
    const int lane = tid & 31, w = tid >> 5;
    const int quad = lane >> 2, qt = lane & 3;
    const int wr   = w >> 2;            // rows wr*32..+31
    const int wc   = w & 3;             // codes wc*32..+31 within tile
    const int wrow = wr * 32;
    const int n0   = blockIdx.x * TM;

    // chunk g (0..31): code tile ct=g>>2, k-pair kcp=g&3 (kc = 2*kcp+h).
    // Stored as two 8KB halves, each in the proven conflict-free layout.
    auto prefetch = [&](int g, int buf) {
#pragma unroll
        for (int q = 0; q < 4; q++) {
            int j  = tid + q * NTH;         // 0..1023 16B-units
            int qq = j & 3, h = (j >> 2) & 1, cl = j >> 3;
            CP16(sb + OFF_B + (uint32_t)buf * CHUNK + h * 8192 + cl * 64 + qq * 16,
                 g_cbh + ((size_t)((g >> 2) * 128 + cl) << 8)
                       + (g & 3) * 64 + h * 32 + qq * 8);
        }
        CP_COMMIT();
    };

    const uint32_t abase = sb + OFF_A2 + (wrow + quad) * A2_STRIDE + qt * 16;
    const uint32_t bbase = sb + OFF_B + (wc * 32 + quad) * 64 + qt * 16;

    for (int d = 0; d < DEPTH; d++) {
        const float* src = (d == 0) ? x : g_resid;
        const bool last = (d == DEPTH - 1);

        prefetch(0, 0);
        prefetch(1, 1);

        // ---- stage: gmem fp32 -> fragment-packed fp16 A2 ----
        {
            int r = tid >> 2, q = tid & 3;
            int n = n0 + r;
            int b = n / HW;
            int hw = n - b * HW;
            const float* sp = src + (size_t)b * (CDIM * HW) + hw;
            uint32_t wbase = sb + OFF_A2 + r * A2_STRIDE + q * 16;
#pragma unroll
            for (int kc = 0; kc < 8; kc++)
#pragma unroll
                for (int jh = 0; jh < 4; jh++) {
                    int k0 = kc * 32 + (jh >> 1) * 16 + (jh & 1) * 8 + q * 2;
                    __half h0 = __float2half_rn(sp[(size_t)k0 * HW]);
                    __half h1 = __float2half_rn(sp[(size_t)(k0 + 1) * HW]);
                    uint32_t v = (uint32_t)__half_as_ushort(h0)
                               | ((uint32_t)__half_as_ushort(h1) << 16);
                    asm volatile("st.shared.u32 [%0], %1;"
                                 :: "r"(wbase + kc * 64 + jh * 4), "r"(v));
                }
        }
        __syncthreads();                   // A2 ready

        float mv[4][2]; int mi[4][2];
#pragma unroll
        for (int i = 0; i < 4; i++)
#pragma unroll
            for (int j = 0; j < 2; j++) { mv[i][j] = -3.0e38f; mi[i][j] = 0; }

        int buf = 0;
        for (int ct = 0; ct < 8; ct++) {
            float acc[8][4];
#pragma unroll
            for (int i = 0; i < 8; i++)
#pragma unroll
                for (int j = 0; j < 4; j++) acc[i][j] = 0.0f;

#pragma unroll
            for (int kcp = 0; kcp < 4; kcp++) {
                int g = ct * 4 + kcp;
                if (g < 31) CP_WAIT1(); else CP_WAIT0();
                __syncthreads();           // chunk g visible; buf (g+2)%3 free
                if (g + 2 < 32) {
                    int nb = buf + 2; if (nb >= 3) nb -= 3;
                    prefetch(g + 2, nb);
                }
#pragma unroll
                for (int h = 0; h < 2; h++) {
                    int kc = kcp * 2 + h;
                    uint32_t Af[4][4], Bf[4][4];
                    uint32_t ab = abase + kc * 64;
                    LDS128(Af[0][0], Af[0][1], Af[0][2], Af[0][3], ab);
                    LDS128(Af[1][0], Af[1][1], Af[1][2], Af[1][3], ab + 8  * A2_STRIDE);
                    LDS128(Af[2][0], Af[2][1], Af[2][2], Af[2][3], ab + 16 * A2_STRIDE);
                    LDS128(Af[3][0], Af[3][1], Af[3][2], Af[3][3], ab + 24 * A2_STRIDE);
                    uint32_t bb = bbase + (uint32_t)buf * CHUNK + h * 8192;
                    LDS128(Bf[0][0], Bf[0][1], Bf[0][2], Bf[0][3], bb);
                    LDS128(Bf[1][0], Bf[1][1], Bf[1][2], Bf[1][3], bb + 512);
                    LDS128(Bf[2][0], Bf[2][1], Bf[2][2], Bf[2][3], bb + 1024);
                    LDS128(Bf[3][0], Bf[3][1], Bf[3][2], Bf[3][3], bb + 1536);
#pragma unroll
                    for (int s = 0; s < 2; s++)
#pragma unroll
                        for (int half = 0; half < 2; half++)
#pragma unroll
                            for (int cf = 0; cf < 4; cf++)
                                mma16(acc[half * 4 + cf],
                                      Af[half * 2][2 * s],     Af[half * 2 + 1][2 * s],
                                      Af[half * 2][2 * s + 1], Af[half * 2 + 1][2 * s + 1],
                                      Bf[cf][2 * s], Bf[cf][2 * s + 1]);
                }
                buf++; if (buf >= 3) buf = 0;
            }

            // fold tile into per-thread top-2 (4 owned rows)
#pragma unroll
            for (int cf = 0; cf < 4; cf++)
#pragma unroll
                for (int half = 0; half < 2; half++)
#pragma unroll
                    for (int j = 0; j < 4; j++) {
                        float v = acc[half * 4 + cf][j];
                        int lr = half * 2 + (j >> 1);
                        int code = ct * 128 + wc * 32 + cf * 8 + qt * 2 + (j & 1);
                        if (v > mv[lr][0]) {
                            mv[lr][1] = mv[lr][0]; mi[lr][1] = mi[lr][0];
                            mv[lr][0] = v;         mi[lr][0] = code;
                        } else if (v > mv[lr][1]) {
                            mv[lr][1] = v;         mi[lr][1] = code;
                        }
                    }
        }

        // ---- merge: 16 partial top-2 sets per row (stride 33); reuses A2 ----
        float* redV = (float*)(smem + OFF_RED);
        int*   redI = (int*)(smem + OFF_RED + 8448);
        __syncthreads();                   // A2 dead from here on
        {
            int slot = wc * 4 + qt;
#pragma unroll
            for (int lr = 0; lr < 4; lr++) {
                int row = wrow + lr * 8 + quad;
                redV[row * 33 + slot * 2 + 0] = mv[lr][0];
                redV[row * 33 + slot * 2 + 1] = mv[lr][1];
                redI[row * 33 + slot * 2 + 0] = mi[lr][0];
                redI[row * 33 + slot * 2 + 1] = mi[lr][1];
            }
        }
        __syncthreads();

        if (tid < TM) {
            float m0 = -3.0e38f, m1 = -3.0e38f, m2 = -3.0e38f, m3 = -3.0e38f;
            int j0 = 0, j1 = 0, j2 = 0, j3 = 0;
#pragma unroll 2
            for (int s = 0; s < 32; s++) {
                float v = redV[tid * 33 + s];
                int   c = redI[tid * 33 + s];
                if (v > m0 || (v == m0 && c < j0)) {
                    m3 = m2; j3 = j2; m2 = m1; j2 = j1; m1 = m0; j1 = j0; m0 = v; j0 = c;
                } else if (v > m1 || (v == m1 && c < j1)) {
                    m3 = m2; j3 = j2; m2 = m1; j2 = j1; m1 = v; j1 = c;
                } else if (v > m2 || (v == m2 && c < j2)) {
                    m3 = m2; j3 = j2; m2 = v; j2 = c;
                } else if (v > m3 || (v == m3 && c < j3)) {
                    m3 = v; j3 = c;
                }
            }
            int c0i = j0;
            int c1i = (m0 - m1 <= TAU) ? j1 : j0;
            int c2i = (m0 - m2 <= TAU) ? j2 : j0;
            int c3i = (m0 - m3 <= TAU) ? j3 : j0;

            // serial ascending-k fp32 chains on EXACT residual (gmem):
            // bitwise-replicates the reference accumulation; u = winner.
            const int n = n0 + tid;
            const int b = n / HW;
            const int hw = n - b * HW;
            const float* sp = src + (size_t)b * (CDIM * HW) + hw;
            const float4* p0 = (const float4*)(cb + (size_t)c0i * CDIM);
            const float4* p1 = (const float4*)(cb + (size_t)c1i * CDIM);
            const float4* p2 = (const float4*)(cb + (size_t)c2i * CDIM);
            const float4* p3 = (const float4*)(cb + (size_t)c3i * CDIM);
            float s0 = 0.0f, s1 = 0.0f, s2 = 0.0f, s3 = 0.0f;
#pragma unroll 4
            for (int q = 0; q < 64; q++) {
                float a0 = sp[(size_t)(q * 4 + 0) * HW];
                float a1 = sp[(size_t)(q * 4 + 1) * HW];
                float a2 = sp[(size_t)(q * 4 + 2) * HW];
                float a3 = sp[(size_t)(q * 4 + 3) * HW];
                float4 b0 = __ldg(p0 + q), b1 = __ldg(p1 + q);
                float4 b2 = __ldg(p2 + q), b3 = __ldg(p3 + q);
                s0 = fmaf(a0, b0.x, s0); s0 = fmaf(a1, b0.y, s0);
                s0 = fmaf(a2, b0.z, s0); s0 = fmaf(a3, b0.w, s0);
                s1 = fmaf(a0, b1.x, s1); s1 = fmaf(a1, b1.y, s1);
                s1 = fmaf(a2, b1.z, s1); s1 = fmaf(a3, b1.w, s1);
                s2 = fmaf(a0, b2.x, s2); s2 = fmaf(a1, b2.y, s2);
                s2 = fmaf(a2, b2.z, s2); s2 = fmaf(a3, b2.w, s2);
                s3 = fmaf(a0, b3.x, s3); s3 = fmaf(a1, b3.y, s3);
                s3 = fmaf(a2, b3.z, s3); s3 = fmaf(a3, b3.w, s3);
            }
            float bp = s0; int bi = c0i;
            if (s1 > bp || (s1 == bp && c1i < bi)) { bp = s1; bi = c1i; }
            if (s2 > bp || (s2 == bp && c2i < bi)) { bp = s2; bi = c2i; }
            if (s3 > bp || (s3 == bp && c3i < bi)) { bp = s3; bi = c3i; }
            scode[tid] = bi;
            su[tid]    = bp;
        }

        // ---- epilogue: resid = src - cb[code]*u  (mul then sub, exact) ----
        float* cbS = (float*)(smem + OFF_RED);     // 32 x 257 floats
        for (int h = 0; h < 2; h++) {              // rows [32h, 32h+32)
            __syncthreads();
            for (int idx = tid; idx < 32 * 256; idx += NTH) {
                int rl = idx >> 8, c = idx & 255;
                cbS[rl * 257 + c] = cb[(size_t)scode[h * 32 + rl] * CDIM + c];
            }
            __syncthreads();
#pragma unroll 4
            for (int it = 0; it < 32; it++) {
                int idx = tid + it * NTH;
                int rl = idx & 31, c = idx >> 5;
                int r = h * 32 + rl;
                int n = n0 + r;
                int b = n / HW;
                int hw = n - b * HW;
                size_t gidx = (size_t)b * (CDIM * HW) + (size_t)c * HW + hw;
                float val = __fsub_rn(src[gidx],
                                      __fmul_rn(su[r], cbS[rl * 257 + c]));
                if (last) out[gidx] = __fsub_rn(x[gidx], val);
                else      g_resid[gidx] = val;
            }
        }
        __syncthreads();   // g_resid + smem ready before next depth
    }
}

extern "C" void kernel_launch(void* const* d_in, const int* in_sizes, int n_in,
                              void* d_out, int out_size)
{
    const float* x  = (const float*)d_in[0];
    const float* cb = (const float*)d_in[1];
    float* out = (float*)d_out;

    cudaFuncSetAttribute(vq_fused, cudaFuncAttributeMaxDynamicSharedMemorySize,
                         SMEM_BYTES);
    prep_cbh<<<1024, 256>>>(cb);
    vq_fused<<<NROWS / TM, NTH, SMEM_BYTES>>>(x, cb, out);
}